// round 5
// baseline (speedup 1.0000x reference)
#include <cuda_runtime.h>
#include <cuda_bf16.h>

// CrossNet collapsed:
//   out = x0 * a3 + Bsum
//   a_{l+1} = a_l + (a_l * d_l + c_l);  d_l = dot(x0_row, W[l]) per-row;
//   c_l = dot(Bsum_l, W[l]) row-independent; Bsum = B0+B1+B2.
// Warp-per-row (8 rows/block), W + Bsum staged in smem once per block.
// x loads front-batched before the fill barrier; each warp reduces only its
// own 3 dot chains (no cross-warp barriers after the prologue).

#define DIMV 256   // float4s per row (DIM = 1024)
#define RPB 8      // rows per block == warps per block

__device__ __forceinline__ float dot4(float4 a, float4 b) {
    return fmaf(a.x, b.x, fmaf(a.y, b.y, fmaf(a.z, b.z, a.w * b.w)));
}

__global__ __launch_bounds__(256, 4) void crossnet_kernel(
    const float4* __restrict__ x0,
    const float4* __restrict__ W,
    const float4* __restrict__ Bm,
    float4* __restrict__ out)
{
    __shared__ float4 sW0[DIMV], sW1[DIMV], sW2[DIMV], sBsum[DIMV];
    __shared__ float sc1[RPB], sc2[RPB];

    const int t = threadIdx.x;
    const int lane = t & 31;
    const int warp = t >> 5;
    const int row = blockIdx.x * RPB + warp;

    // ---- front-batched DRAM reads: 8 independent loads in flight ----
    const float4* xrow = x0 + (size_t)row * DIMV;
    float4 x[8];
#pragma unroll
    for (int p = 0; p < 8; ++p) x[p] = xrow[p * 32 + lane];

    // ---- prologue: stage W / Bsum into smem, reduce c1/c2 ----
    {
        float4 w1 = W[DIMV + t];
        float4 w2 = W[2 * DIMV + t];
        float4 b0 = Bm[t];
        float4 b1 = Bm[DIMV + t];
        float4 b2 = Bm[2 * DIMV + t];
        sW0[t] = W[t];
        sW1[t] = w1;
        sW2[t] = w2;

        float4 b01 = make_float4(b0.x + b1.x, b0.y + b1.y, b0.z + b1.z, b0.w + b1.w);
        sBsum[t] = make_float4(b01.x + b2.x, b01.y + b2.y, b01.z + b2.z, b01.w + b2.w);

        float c1 = dot4(b0, w1);    // dot(B0, W1) partial
        float c2 = dot4(b01, w2);   // dot(B0+B1, W2) partial
#pragma unroll
        for (int o = 16; o > 0; o >>= 1) {
            c1 += __shfl_xor_sync(0xffffffffu, c1, o);
            c2 += __shfl_xor_sync(0xffffffffu, c2, o);
        }
        if (lane == 0) { sc1[warp] = c1; sc2[warp] = c2; }
    }
    __syncthreads();   // the ONLY barrier

    // ---- per-warp dots from smem ----
    float d0 = 0.f, d1 = 0.f, d2 = 0.f;
#pragma unroll
    for (int p = 0; p < 8; ++p) {
        const int c = p * 32 + lane;
        d0 = fmaf(x[p].x, sW0[c].x, fmaf(x[p].y, sW0[c].y,
             fmaf(x[p].z, sW0[c].z, fmaf(x[p].w, sW0[c].w, d0))));
        d1 = fmaf(x[p].x, sW1[c].x, fmaf(x[p].y, sW1[c].y,
             fmaf(x[p].z, sW1[c].z, fmaf(x[p].w, sW1[c].w, d1))));
        d2 = fmaf(x[p].x, sW2[c].x, fmaf(x[p].y, sW2[c].y,
             fmaf(x[p].z, sW2[c].z, fmaf(x[p].w, sW2[c].w, d2))));
    }

    // three independent shuffle chains; every lane ends with the full sum
#pragma unroll
    for (int o = 16; o > 0; o >>= 1) {
        d0 += __shfl_xor_sync(0xffffffffu, d0, o);
        d1 += __shfl_xor_sync(0xffffffffu, d1, o);
        d2 += __shfl_xor_sync(0xffffffffu, d2, o);
    }

    float C1 = 0.f, C2 = 0.f;
#pragma unroll
    for (int w = 0; w < RPB; ++w) { C1 += sc1[w]; C2 += sc2[w]; }  // broadcast LDS

    // scalar recurrence (c0 == 0 exactly), redundant per lane
    float a = 1.0f;
    float s = a * d0;          a += s;
    s = fmaf(a, d1, C1);       a += s;
    s = fmaf(a, d2, C2);       a += s;

    // ---- fused store ----
    float4* orow = out + (size_t)row * DIMV;
#pragma unroll
    for (int p = 0; p < 8; ++p) {
        const int c = p * 32 + lane;
        float4 bs = sBsum[c];
        float4 o;
        o.x = fmaf(x[p].x, a, bs.x);
        o.y = fmaf(x[p].y, a, bs.y);
        o.z = fmaf(x[p].z, a, bs.z);
        o.w = fmaf(x[p].w, a, bs.w);
        orow[c] = o;
    }
}

extern "C" void kernel_launch(void* const* d_in, const int* in_sizes, int n_in,
                              void* d_out, int out_size)
{
    const float4* x0 = (const float4*)d_in[0];
    const float4* W  = (const float4*)d_in[1];
    const float4* B  = (const float4*)d_in[2];
    float4* out = (float4*)d_out;

    const int batch = in_sizes[0] / 1024;   // 16384, divisible by RPB
    crossnet_kernel<<<batch / RPB, 256>>>(x0, W, B, out);
}

// round 6
// speedup vs baseline: 1.1358x; 1.1358x over previous
#include <cuda_runtime.h>
#include <cuda_bf16.h>

// CrossNet collapsed:
//   out = x0 * a3 + Bsum
//   a_{l+1} = a_l + (a_l * d_l + c_l);  d_l = dot(x0_row, W[l]) per-row;
//   c_l = dot(Bsum_l, W[l]) row-independent; Bsum = B0+B1+B2.
//
// R=4 rows per block (256 thr, thread t owns float4 column t of all 4 rows).
// W/B live in REGISTERS (one LDG set per thread, L2-resident across blocks)
// -> zero LDS in the dot phase (l1tex was the contended pipe in R5).
// Reduction: 14 shuffle chains -> one smem exchange -> ONE barrier -> every
// warp redundantly finishes (no warp-0 serialization, no second barrier).

#define DIMV 256   // float4s per row (DIM = 1024)
#define R 4        // rows per block

__device__ __forceinline__ float dot4(float4 a, float4 b) {
    return fmaf(a.x, b.x, fmaf(a.y, b.y, fmaf(a.z, b.z, a.w * b.w)));
}

__global__ __launch_bounds__(256, 4) void crossnet_kernel(
    const float4* __restrict__ x0,
    const float4* __restrict__ W,
    const float4* __restrict__ Bm,
    float4* __restrict__ out)
{
    __shared__ float sd[8][16];   // [warp][chain 0..13], padded to 16

    const int t = threadIdx.x;
    const int lane = t & 31;
    const int warp = t >> 5;
    const int row0 = blockIdx.x * R;

    // ---- front-batched DRAM reads (the only DRAM traffic in) ----
    float4 x[R];
#pragma unroll
    for (int r = 0; r < R; ++r)
        x[r] = x0[(size_t)(row0 + r) * DIMV + t];

    // ---- L2-resident W/B into registers ----
    float4 w0 = W[t];
    float4 w1 = W[DIMV + t];
    float4 w2 = W[2 * DIMV + t];
    float4 b0 = Bm[t];
    float4 b1 = Bm[DIMV + t];
    float4 b2 = Bm[2 * DIMV + t];

    float4 bs01 = make_float4(b0.x + b1.x, b0.y + b1.y, b0.z + b1.z, b0.w + b1.w);
    float4 bsum = make_float4(bs01.x + b2.x, bs01.y + b2.y, bs01.z + b2.z, bs01.w + b2.w);

    // 14 reduction chains: q = 3r+l -> d_l(row r); 12 -> c1; 13 -> c2
    float v[14];
#pragma unroll
    for (int r = 0; r < R; ++r) {
        v[3 * r + 0] = dot4(x[r], w0);
        v[3 * r + 1] = dot4(x[r], w1);
        v[3 * r + 2] = dot4(x[r], w2);
    }
    v[12] = dot4(b0, w1);
    v[13] = dot4(bs01, w2);

#pragma unroll
    for (int o = 16; o > 0; o >>= 1) {
#pragma unroll
        for (int q = 0; q < 14; ++q)
            v[q] += __shfl_xor_sync(0xffffffffu, v[q], o);
    }

    if (lane < 14) sd[warp][lane] = v[lane];
    __syncthreads();   // the ONLY barrier

    // ---- every warp redundantly finishes the reduction ----
    float S = 0.0f;
    if (lane < 14) {
#pragma unroll
        for (int w = 0; w < 8; ++w) S += sd[w][lane];   // conflict-free
    }

    // lanes 0..3 assemble row scalars and run the recurrence
    float d0 = __shfl_sync(0xffffffffu, S, (lane < R) ? 3 * lane + 0 : 0);
    float d1 = __shfl_sync(0xffffffffu, S, (lane < R) ? 3 * lane + 1 : 0);
    float d2 = __shfl_sync(0xffffffffu, S, (lane < R) ? 3 * lane + 2 : 0);
    float C1 = __shfl_sync(0xffffffffu, S, 12);
    float C2 = __shfl_sync(0xffffffffu, S, 13);

    float a = 1.0f;
    {
        float s = a * d0;          a += s;   // c0 == 0 exactly
        s = fmaf(a, d1, C1);       a += s;
        s = fmaf(a, d2, C2);       a += s;
    }
    const float a0 = __shfl_sync(0xffffffffu, a, 0);
    const float a1 = __shfl_sync(0xffffffffu, a, 1);
    const float a2 = __shfl_sync(0xffffffffu, a, 2);
    const float a3 = __shfl_sync(0xffffffffu, a, 3);
    const float ar[R] = {a0, a1, a2, a3};

    // ---- fused store (the only DRAM traffic out) ----
#pragma unroll
    for (int r = 0; r < R; ++r) {
        float4 o;
        o.x = fmaf(x[r].x, ar[r], bsum.x);
        o.y = fmaf(x[r].y, ar[r], bsum.y);
        o.z = fmaf(x[r].z, ar[r], bsum.z);
        o.w = fmaf(x[r].w, ar[r], bsum.w);
        out[(size_t)(row0 + r) * DIMV + t] = o;
    }
}

extern "C" void kernel_launch(void* const* d_in, const int* in_sizes, int n_in,
                              void* d_out, int out_size)
{
    const float4* x0 = (const float4*)d_in[0];
    const float4* W  = (const float4*)d_in[1];
    const float4* B  = (const float4*)d_in[2];
    float4* out = (float4*)d_out;

    const int batch = in_sizes[0] / 1024;   // 16384, divisible by R
    crossnet_kernel<<<batch / R, 256>>>(x0, W, B, out);
}